// round 14
// baseline (speedup 1.0000x reference)
#include <cuda_runtime.h>

#define NK 5000
#define BB 512
#define TT 100
#define HS 256   // hash slots (power of 2), load factor <= 99/256

__device__ __forceinline__ float sigm(float x) {
    return 1.f / (1.f + __expf(-x));
}

__device__ __forceinline__ int hashk(int k) {
    return (int)(((unsigned)k * 2654435761u) >> 20) & (HS - 1);
}

// highest set bit index <= cap over a 4x32 mask, 0 if none (bit 0 is never set)
__device__ __forceinline__ int hibit_le(const unsigned m[4], int cap) {
    const int w = cap >> 5;
    const unsigned inc = (2u << (cap & 31)) - 1u;   // bits 0..cap&31 (31 -> all)
    int r = 0;
    #pragma unroll
    for (int j = 3; j >= 0; --j) {
        unsigned mm = (j > w) ? 0u : ((j == w) ? (m[j] & inc) : m[j]);
        if (mm && r == 0) r = (j << 5) + 31 - __clz(mm);
    }
    return r;
}

// One CTA per batch row, single kernel.
//
// BKT recurrence carries dependencies only through index collisions:
//   skill(t) = pred(prev(t)),  prev(t) = last t'<t with pk(t')==pk(t), else init
//   cs(t)    = pred(tc(t)),    tc(t)   = last t'<=t with pk(t')==ck(t), else init
// The dependency forest (~depth 2-3 for 100 draws from 5000 keys) is resolved
// in depth-ordered parallel rounds. prev/tc/islast come from an O(T) SMEM
// hash: CAS-insert pk keys, atomicOr a 128-bit timestep mask per key, then
// CLZ-scan the masks.
//
// Warps 0-3: search + rounds + probs + fixup. Warps 4-7 (overlapped): stream
// init state sigmoid(logits[:,4]) to gmem via STG.128.
__global__ __launch_bounds__(256, 1) void bkt_kernel(
    const int* __restrict__ prev_kc,
    const int* __restrict__ curr_kc,
    const int* __restrict__ prev_corr,
    const float* __restrict__ logits,
    float* __restrict__ out)
{
    __shared__ int      s_hkey[HS];
    __shared__ unsigned s_hmask[HS][4];
    __shared__ int      s_prev[TT];
    __shared__ float    s_pred[TT];
    __shared__ int      s_wmax[4];

    const int b = blockIdx.x;
    const int tid = threadIdx.x;
    float* probOut  = out + b * TT;
    float* stateOut = out + BB * TT + b * NK;   // 16B-aligned for every b

    // Survive into the post-sync fixup:
    int   pk = -1;
    bool  doFix = false;
    float myPred = 0.f;

    if (tid < 128) {
        const int  t      = tid;
        const bool active = (t < TT);

        // ---- hash init (2 slots per thread) ----
        #pragma unroll
        for (int j = 0; j < 2; ++j) {
            const int s = tid + j * 128;
            s_hkey[s] = -1;
            s_hmask[s][0] = 0u; s_hmask[s][1] = 0u;
            s_hmask[s][2] = 0u; s_hmask[s][3] = 0u;
        }

        // ---- Phase A: gathers, sigmoids, per-thread chain constants ----
        int   ck = 0;
        float Cx = 0.f, Cy = 0.f, Cz = 0.f, Cw = 0.f;
        float Px = 0.f, Py = 0.f, skill0 = 0.f, ckinit = 0.f;
        if (active) {
            ck = curr_kc[b * TT + t];
            if (t >= 1) {
                pk = prev_kc[b * TT + t];
                const int c = prev_corr[b * TT + t];
                const float* rp = logits + pk * 5;
                const float pvx = sigm(rp[0]);
                const float pvy = sigm(rp[1]);
                const float pvz = sigm(rp[2]);
                const float pvw = sigm(rp[3]);
                skill0 = sigm(rp[4]);
                const float p2 = c ? pvz : 1.f - pvz;   // p_out[0]
                const float p3 = c ? pvw : 1.f - pvw;   // p_out[1]
                Cx = p2;  Cy = p3 - p2;  Cz = pvx;
                Cw = (1.f - pvy - pvx) * p3;            // pred = Cz + Cw*sk/den
            }
            const float* cp = logits + ck * 5;
            const float cvz = sigm(cp[2]);
            const float cvw = sigm(cp[3]);
            ckinit = sigm(cp[4]);
            Px = cvz;  Py = cvw - cvz;                  // prob = fma(cs,Py,Px)
        }
        asm volatile("bar.sync 1, 128;" ::: "memory");  // hash table zeroed

        // ---- Insert: claim slot for pk, set timestep bit ----
        int myslot = -1;
        if (active && t >= 1) {
            int s = hashk(pk);
            while (true) {
                const int old = atomicCAS(&s_hkey[s], -1, pk);
                if (old == -1 || old == pk) break;
                s = (s + 1) & (HS - 1);
            }
            myslot = s;
            atomicOr(&s_hmask[s][t >> 5], 1u << (t & 31));
        }
        asm volatile("bar.sync 1, 128;" ::: "memory");  // table stable

        // ---- Lookups: prev / islast (own slot), tc (probe ck) ----
        int prev = 0, tc = 0;
        bool islast = true;
        if (active) {
            if (t >= 1) {
                unsigned m[4];
                m[0] = s_hmask[myslot][0]; m[1] = s_hmask[myslot][1];
                m[2] = s_hmask[myslot][2]; m[3] = s_hmask[myslot][3];
                // highest bit strictly below t
                if (t > 1) {
                    unsigned mb[4];
                    const int w = (t - 1) >> 5;
                    #pragma unroll
                    for (int j = 0; j < 4; ++j) mb[j] = m[j];
                    prev = hibit_le(mb, t - 1);
                    (void)w;
                }
                // any bit strictly above t?
                {
                    const int w = t >> 5;
                    unsigned above = m[w] & ~((2u << (t & 31)) - 1u);
                    #pragma unroll
                    for (int j = 0; j < 4; ++j)
                        if (j > w) above |= m[j];
                    islast = (above == 0u);
                }
                s_prev[t] = prev;
            }
            // tc: probe for ck (absent -> 0)
            {
                int s = hashk(ck);
                int fs = -1;
                while (true) {
                    const int kk = s_hkey[s];
                    if (kk == ck) { fs = s; break; }
                    if (kk == -1) break;
                    s = (s + 1) & (HS - 1);
                }
                if (fs >= 0) {
                    unsigned m2[4];
                    m2[0] = s_hmask[fs][0]; m2[1] = s_hmask[fs][1];
                    m2[2] = s_hmask[fs][2]; m2[3] = s_hmask[fs][3];
                    tc = hibit_le(m2, t);
                }
            }
        }
        asm volatile("bar.sync 1, 128;" ::: "memory");  // s_prev ready

        // ---- Depth in the dependency forest ----
        int depth = 0;
        if (active && t >= 1)
            for (int c2 = prev; c2 != 0; c2 = s_prev[c2]) depth++;
        const int wm = __reduce_max_sync(0xffffffffu, depth);
        if ((tid & 31) == 0) s_wmax[tid >> 5] = wm;
        asm volatile("bar.sync 1, 128;" ::: "memory");
        const int maxd = max(max(s_wmax[0], s_wmax[1]),
                             max(s_wmax[2], s_wmax[3]));

        // ---- Rounds: resolve preds in depth order ----
        for (int r = 0; r <= maxd; ++r) {
            if (active && t >= 1 && depth == r) {
                const float sk  = prev ? s_pred[prev] : skill0;
                const float den = fmaf(Cy, sk, Cx);
                myPred = Cz + __fdividef(Cw * sk, den);
                s_pred[t] = myPred;
            }
            asm volatile("bar.sync 1, 128;" ::: "memory");
        }

        // ---- Probs ----
        if (active) {
            const float cs = tc ? s_pred[tc] : ckinit;
            probOut[t] = fmaf(cs, Py, Px);
        }
        doFix = active && (t >= 1) && islast;
    } else {
        // ---- Overlapped: stream init state, 4 elems/thread, STG.128 ----
        const int lane = tid - 128;                   // 0..127
        float4* so4 = (float4*)stateOut;
        for (int k4 = lane; k4 < NK / 4; k4 += 128) {
            const int kb = k4 * 4;
            float4 v;
            v.x = sigm(logits[(kb + 0) * 5 + 4]);
            v.y = sigm(logits[(kb + 1) * 5 + 4]);
            v.z = sigm(logits[(kb + 2) * 5 + 4]);
            v.w = sigm(logits[(kb + 3) * 5 + 4]);
            so4[k4] = v;
        }
    }
    __syncthreads();

    // ---- Fixup: last occurrence of each pk overwrites with final pred ----
    if (doFix) stateOut[pk] = myPred;
}

extern "C" void kernel_launch(void* const* d_in, const int* in_sizes, int n_in,
                              void* d_out, int out_size) {
    const int*   prev_kc   = (const int*)d_in[0];
    const int*   curr_kc   = (const int*)d_in[1];
    const int*   prev_corr = (const int*)d_in[2];
    const float* logits    = (const float*)d_in[3];
    float*       out       = (float*)d_out;

    bkt_kernel<<<BB, 256>>>(prev_kc, curr_kc, prev_corr, logits, out);
}